// round 2
// baseline (speedup 1.0000x reference)
#include <cuda_runtime.h>
#include <math.h>

#define B_ 4
#define C_ 256
#define H_ 128
#define W_ 128
#define HW_ (H_*W_)
#define NPIX_ (B_*HW_)
#define PTILE 32
#define KT 16

// Scratch: x transposed to NHWC, weights transposed to k-major.
__device__ float g_xt[(size_t)NPIX_ * C_];   // 64 MB
__device__ float g_w0t[C_ * C_];
__device__ float g_w1t[C_ * C_];

// ---------------------------------------------------------------------------
// Transpose x: [B][C][HW] -> g_xt [B][HW][C]
// ---------------------------------------------------------------------------
__global__ void k_tx(const float* __restrict__ x) {
    __shared__ float t[32][33];
    int b = blockIdx.z, s0 = blockIdx.x * 32, c0 = blockIdx.y * 32;
    int tx = threadIdx.x, ty = threadIdx.y;
    const float* xi = x + (size_t)b * C_ * HW_;
    float* xo = g_xt + (size_t)b * HW_ * C_;
#pragma unroll
    for (int i = 0; i < 32; i += 8)
        t[ty + i][tx] = xi[(size_t)(c0 + ty + i) * HW_ + s0 + tx];
    __syncthreads();
#pragma unroll
    for (int i = 0; i < 32; i += 8)
        xo[(size_t)(s0 + ty + i) * C_ + c0 + tx] = t[tx][ty + i];
}

// Transpose weights: w[o][c] -> wt[c][o]  (z=0 -> w0, z=1 -> w1)
__global__ void k_tw(const float* __restrict__ w0, const float* __restrict__ w1) {
    __shared__ float t[32][33];
    const float* wi = blockIdx.z ? w1 : w0;
    float* wo = blockIdx.z ? g_w1t : g_w0t;
    int o0 = blockIdx.y * 32, c0 = blockIdx.x * 32;
    int tx = threadIdx.x, ty = threadIdx.y;
#pragma unroll
    for (int i = 0; i < 32; i += 8)
        t[ty + i][tx] = wi[(o0 + ty + i) * C_ + c0 + tx];
    __syncthreads();
#pragma unroll
    for (int i = 0; i < 32; i += 8)
        wo[(c0 + ty + i) * C_ + o0 + tx] = t[tx][ty + i];
}

// ---------------------------------------------------------------------------
// Fused: deformable gather+max  ->  dual GEMM  ->  norm-dot epilogue
// Block: 256 threads, 32 consecutive pixels on one row.
// ---------------------------------------------------------------------------
__global__ __launch_bounds__(256)
void k_main(const float* __restrict__ offset, const float* __restrict__ b0,
            const float* __restrict__ b1, float* __restrict__ out) {
    extern __shared__ float sm[];
    float* qs   = sm;                    // [256][33]
    float* xs   = qs + 256 * 33;         // [256][33]
    float* w0s  = xs + 256 * 33;         // [KT][256]
    float* w1s  = w0s + KT * 256;        // [KT][256]
    float* offs = w1s + KT * 256;        // [18][32]

    const int tid  = threadIdx.x;
    const int base = blockIdx.x * PTILE;
    const int b    = base / HW_;
    const int rem  = base % HW_;
    const int y    = rem / W_;
    const int x0   = rem % W_;

    // offsets for the 32 pixels
    for (int i = tid; i < 18 * PTILE; i += 256) {
        int j = i >> 5, p = i & 31;
        offs[i] = offset[((size_t)b * 18 + j) * HW_ + y * W_ + x0 + p];
    }
    __syncthreads();

    const float* xtb = g_xt + (size_t)b * HW_ * C_;
    const int sub = tid & 7;      // 8 threads per pixel, 32 channels each (8 float4)
    const int p   = tid >> 3;
    const int pxi = x0 + p;

    // stage x (key input) for this pixel into xs[c][p]
    {
        const float4* xp = (const float4*)(xtb + (size_t)(y * W_ + pxi) * C_);
#pragma unroll
        for (int i = 0; i < 8; i++) {
            float4 v = xp[sub + 8 * i];
            int c = 4 * (sub + 8 * i);
            xs[(c + 0) * 33 + p] = v.x;
            xs[(c + 1) * 33 + p] = v.y;
            xs[(c + 2) * 33 + p] = v.z;
            xs[(c + 3) * 33 + p] = v.w;
        }
    }

    // deformable 3x3 unfold fused with max over the 9 sample points
    float4 qm[8];
#pragma unroll
    for (int i = 0; i < 8; i++) { qm[i].x = qm[i].y = qm[i].z = qm[i].w = -3.4e38f; }

#pragma unroll
    for (int k = 0; k < 9; k++) {
        const int kh = k / 3 - 1, kw = k % 3 - 1;
        float py  = (float)(y + kh)   + offs[(2 * k) * 32 + p];
        float pxx = (float)(pxi + kw) + offs[(2 * k + 1) * 32 + p];
        float fy = floorf(py), fx = floorf(pxx);
        float wy = py - fy, wx = pxx - fx;
        int iy = (int)fy, ix = (int)fx;

        float4 acc[8];
#pragma unroll
        for (int i = 0; i < 8; i++) { acc[i].x = acc[i].y = acc[i].z = acc[i].w = 0.f; }

        float cw[4] = { (1.f - wy) * (1.f - wx), (1.f - wy) * wx,
                        wy * (1.f - wx),         wy * wx };
        int cy[4] = { iy, iy, iy + 1, iy + 1 };
        int cx[4] = { ix, ix + 1, ix, ix + 1 };
#pragma unroll
        for (int c4 = 0; c4 < 4; c4++) {
            if (cy[c4] >= 0 && cy[c4] < H_ && cx[c4] >= 0 && cx[c4] < W_) {
                const float4* cp = (const float4*)(xtb + (size_t)(cy[c4] * W_ + cx[c4]) * C_);
                float w = cw[c4];
#pragma unroll
                for (int i = 0; i < 8; i++) {
                    float4 v = cp[sub + 8 * i];
                    acc[i].x = fmaf(w, v.x, acc[i].x);
                    acc[i].y = fmaf(w, v.y, acc[i].y);
                    acc[i].z = fmaf(w, v.z, acc[i].z);
                    acc[i].w = fmaf(w, v.w, acc[i].w);
                }
            }
        }
#pragma unroll
        for (int i = 0; i < 8; i++) {
            qm[i].x = fmaxf(qm[i].x, acc[i].x);
            qm[i].y = fmaxf(qm[i].y, acc[i].y);
            qm[i].z = fmaxf(qm[i].z, acc[i].z);
            qm[i].w = fmaxf(qm[i].w, acc[i].w);
        }
    }
#pragma unroll
    for (int i = 0; i < 8; i++) {
        int c = 4 * (sub + 8 * i);
        qs[(c + 0) * 33 + p] = qm[i].x;
        qs[(c + 1) * 33 + p] = qm[i].y;
        qs[(c + 2) * 33 + p] = qm[i].z;
        qs[(c + 3) * 33 + p] = qm[i].w;
    }
    __syncthreads();

    // --- dual GEMM: query = W0 q + b0, key = W1 x + b1, never materialized ---
    const int to = tid & 31;   // output-channel group (o = to + 32*i)
    const int tp = tid >> 5;   // pixel group (p = tp*4 + j); warp == tp
    float aQ[8][4], aK[8][4];
#pragma unroll
    for (int i = 0; i < 8; i++) {
        float bq = b0[to + 32 * i], bk = b1[to + 32 * i];
#pragma unroll
        for (int j = 0; j < 4; j++) { aQ[i][j] = bq; aK[i][j] = bk; }
    }

    for (int kb = 0; kb < C_; kb += KT) {
        __syncthreads();
#pragma unroll
        for (int t = 0; t < KT; t++) {
            w0s[t * 256 + tid] = g_w0t[(kb + t) * 256 + tid];
            w1s[t * 256 + tid] = g_w1t[(kb + t) * 256 + tid];
        }
        __syncthreads();
#pragma unroll
        for (int kk = 0; kk < KT; kk++) {
            float qv[4], xv[4];
#pragma unroll
            for (int j = 0; j < 4; j++) {
                qv[j] = qs[(kb + kk) * 33 + tp * 4 + j];
                xv[j] = xs[(kb + kk) * 33 + tp * 4 + j];
            }
#pragma unroll
            for (int i = 0; i < 8; i++) {
                float w0v = w0s[kk * 256 + to + 32 * i];
                float w1v = w1s[kk * 256 + to + 32 * i];
#pragma unroll
                for (int j = 0; j < 4; j++) {
                    aQ[i][j] = fmaf(w0v, qv[j], aQ[i][j]);
                    aK[i][j] = fmaf(w1v, xv[j], aK[i][j]);
                }
            }
        }
    }

    // --- epilogue: 5 stats per pixel, warp reduction over the 32 'to' lanes ---
#pragma unroll
    for (int j = 0; j < 4; j++) {
        float sq = 0.f, sk = 0.f, sqq = 0.f, skk = 0.f, sqk = 0.f;
#pragma unroll
        for (int i = 0; i < 8; i++) {
            float q = aQ[i][j], k2 = aK[i][j];
            sq += q; sk += k2;
            sqq = fmaf(q, q, sqq);
            skk = fmaf(k2, k2, skk);
            sqk = fmaf(q, k2, sqk);
        }
#pragma unroll
        for (int o = 16; o > 0; o >>= 1) {
            sq  += __shfl_xor_sync(0xffffffffu, sq,  o);
            sk  += __shfl_xor_sync(0xffffffffu, sk,  o);
            sqq += __shfl_xor_sync(0xffffffffu, sqq, o);
            skk += __shfl_xor_sync(0xffffffffu, skk, o);
            sqk += __shfl_xor_sync(0xffffffffu, sqk, o);
        }
        if (to == j) {
            const float inv = 1.f / 256.f;
            float num = sqk - sq * sk * inv;
            float dq  = sqq - sq * sq * inv + 1e-5f;
            float dk  = skk - sk * sk * inv + 1e-5f;
            out[base + tp * 4 + j] = num * rsqrtf(dq) * rsqrtf(dk);
        }
    }
}

// ---------------------------------------------------------------------------
extern "C" void kernel_launch(void* const* d_in, const int* in_sizes, int n_in,
                              void* d_out, int out_size) {
    const float* x      = (const float*)d_in[0];
    const float* offset = (const float*)d_in[1];
    const float* w0     = (const float*)d_in[2];
    const float* b0     = (const float*)d_in[3];
    const float* w1     = (const float*)d_in[4];
    const float* b1     = (const float*)d_in[5];
    float* out = (float*)d_out;

    k_tx<<<dim3(HW_ / 32, C_ / 32, B_), dim3(32, 8)>>>(x);
    k_tw<<<dim3(8, 8, 2), dim3(32, 8)>>>(w0, w1);

    size_t smem = (size_t)(256 * 33 * 2 + KT * 256 * 2 + 18 * 32) * sizeof(float);
    cudaFuncSetAttribute(k_main, cudaFuncAttributeMaxDynamicSharedMemorySize, (int)smem);
    k_main<<<NPIX_ / PTILE, 256, smem>>>(offset, b0, b1, out);
}

// round 3
// speedup vs baseline: 1.1032x; 1.1032x over previous
#include <cuda_runtime.h>
#include <math.h>

#define B_ 4
#define C_ 256
#define H_ 128
#define W_ 128
#define HW_ (H_*W_)
#define NPIX_ (B_*HW_)
#define PTILE 64
#define KT 8
#define QSTR 66   // qs/xs row stride in floats (even -> 8B-aligned pixel pairs)

// Scratch: x transposed to NHWC, weights transposed to k-major.
__device__ float g_xt[(size_t)NPIX_ * C_];   // 64 MB
__device__ float g_w0t[C_ * C_];
__device__ float g_w1t[C_ * C_];

typedef unsigned long long u64;

__device__ __forceinline__ u64 pk2(float lo, float hi) {
    u64 r; asm("mov.b64 %0, {%1,%2};" : "=l"(r) : "f"(lo), "f"(hi)); return r;
}
__device__ __forceinline__ void upk2(u64 v, float& lo, float& hi) {
    asm("mov.b64 {%0,%1}, %2;" : "=f"(lo), "=f"(hi) : "l"(v));
}
__device__ __forceinline__ void fma2(u64& d, u64 a, u64 b) {
    asm("fma.rn.f32x2 %0, %1, %2, %0;" : "+l"(d) : "l"(a), "l"(b));
}

// ---------------------------------------------------------------------------
// Transpose x: [B][C][HW] -> g_xt [B][HW][C]
// ---------------------------------------------------------------------------
__global__ void k_tx(const float* __restrict__ x) {
    __shared__ float t[32][33];
    int b = blockIdx.z, s0 = blockIdx.x * 32, c0 = blockIdx.y * 32;
    int tx = threadIdx.x, ty = threadIdx.y;
    const float* xi = x + (size_t)b * C_ * HW_;
    float* xo = g_xt + (size_t)b * HW_ * C_;
#pragma unroll
    for (int i = 0; i < 32; i += 8)
        t[ty + i][tx] = xi[(size_t)(c0 + ty + i) * HW_ + s0 + tx];
    __syncthreads();
#pragma unroll
    for (int i = 0; i < 32; i += 8)
        xo[(size_t)(s0 + ty + i) * C_ + c0 + tx] = t[tx][ty + i];
}

// Transpose weights: w[o][c] -> wt[c][o]
__global__ void k_tw(const float* __restrict__ w0, const float* __restrict__ w1) {
    __shared__ float t[32][33];
    const float* wi = blockIdx.z ? w1 : w0;
    float* wo = blockIdx.z ? g_w1t : g_w0t;
    int o0 = blockIdx.y * 32, c0 = blockIdx.x * 32;
    int tx = threadIdx.x, ty = threadIdx.y;
#pragma unroll
    for (int i = 0; i < 32; i += 8)
        t[ty + i][tx] = wi[(o0 + ty + i) * C_ + c0 + tx];
    __syncthreads();
#pragma unroll
    for (int i = 0; i < 32; i += 8)
        wo[(c0 + ty + i) * C_ + o0 + tx] = t[tx][ty + i];
}

// ---------------------------------------------------------------------------
// Fused: deformable gather+max -> dual GEMM (f32x2) -> norm-dot epilogue
// Block: 256 threads, 64 consecutive pixels on one row.
// ---------------------------------------------------------------------------
__global__ __launch_bounds__(256, 1)
void k_main(const float* __restrict__ offset, const float* __restrict__ b0,
            const float* __restrict__ b1, float* __restrict__ out) {
    extern __shared__ float sm[];
    float* qs   = sm;                     // [C_][QSTR]
    float* xs   = qs + C_ * QSTR;         // [C_][QSTR]
    float* w0s  = xs + C_ * QSTR;         // [KT][256]
    float* w1s  = w0s + KT * 256;         // [KT][256]
    float* offs = w1s + KT * 256;         // [18][PTILE]

    const int tid  = threadIdx.x;
    const int base = blockIdx.x * PTILE;
    const int b    = base / HW_;
    const int rem  = base % HW_;
    const int y    = rem / W_;
    const int x0   = rem % W_;

    // offsets for the 64 pixels
    for (int i = tid; i < 18 * PTILE; i += 256) {
        int j = i / PTILE, p = i % PTILE;
        offs[i] = offset[((size_t)b * 18 + j) * HW_ + y * W_ + x0 + p];
    }
    __syncthreads();

    const float* xtb = g_xt + (size_t)b * HW_ * C_;
    const int sub = tid & 3;      // 4 threads per pixel, 64 channels each (16 float4)
    const int p   = tid >> 2;
    const int pxi = x0 + p;

    // stage x (key input) into xs[c][p]
    {
        const float4* xp = (const float4*)(xtb + (size_t)(y * W_ + pxi) * C_);
#pragma unroll
        for (int i = 0; i < 16; i++) {
            float4 v = xp[sub + 4 * i];
            int c = 4 * (sub + 4 * i);
            xs[(c + 0) * QSTR + p] = v.x;
            xs[(c + 1) * QSTR + p] = v.y;
            xs[(c + 2) * QSTR + p] = v.z;
            xs[(c + 3) * QSTR + p] = v.w;
        }
    }

    // deformable 3x3 unfold fused with max over the 9 sample points
    float4 qm[16];
#pragma unroll
    for (int i = 0; i < 16; i++) { qm[i].x = qm[i].y = qm[i].z = qm[i].w = -3.4e38f; }

#pragma unroll
    for (int k = 0; k < 9; k++) {
        const int kh = k / 3 - 1, kw = k % 3 - 1;
        float py  = (float)(y + kh)   + offs[(2 * k) * PTILE + p];
        float pxx = (float)(pxi + kw) + offs[(2 * k + 1) * PTILE + p];
        float fy = floorf(py), fx = floorf(pxx);
        float wy = py - fy, wx = pxx - fx;
        int iy = (int)fy, ix = (int)fx;

        float4 acc[16];
#pragma unroll
        for (int i = 0; i < 16; i++) { acc[i].x = acc[i].y = acc[i].z = acc[i].w = 0.f; }

        float cw[4] = { (1.f - wy) * (1.f - wx), (1.f - wy) * wx,
                        wy * (1.f - wx),         wy * wx };
        int cy[4] = { iy, iy, iy + 1, iy + 1 };
        int cx[4] = { ix, ix + 1, ix, ix + 1 };
#pragma unroll
        for (int c4 = 0; c4 < 4; c4++) {
            if (cy[c4] >= 0 && cy[c4] < H_ && cx[c4] >= 0 && cx[c4] < W_) {
                const float4* cp = (const float4*)(xtb + (size_t)(cy[c4] * W_ + cx[c4]) * C_);
                float w = cw[c4];
#pragma unroll
                for (int i = 0; i < 16; i++) {
                    float4 v = cp[sub + 4 * i];
                    acc[i].x = fmaf(w, v.x, acc[i].x);
                    acc[i].y = fmaf(w, v.y, acc[i].y);
                    acc[i].z = fmaf(w, v.z, acc[i].z);
                    acc[i].w = fmaf(w, v.w, acc[i].w);
                }
            }
        }
#pragma unroll
        for (int i = 0; i < 16; i++) {
            qm[i].x = fmaxf(qm[i].x, acc[i].x);
            qm[i].y = fmaxf(qm[i].y, acc[i].y);
            qm[i].z = fmaxf(qm[i].z, acc[i].z);
            qm[i].w = fmaxf(qm[i].w, acc[i].w);
        }
    }
#pragma unroll
    for (int i = 0; i < 16; i++) {
        int c = 4 * (sub + 4 * i);
        qs[(c + 0) * QSTR + p] = qm[i].x;
        qs[(c + 1) * QSTR + p] = qm[i].y;
        qs[(c + 2) * QSTR + p] = qm[i].z;
        qs[(c + 3) * QSTR + p] = qm[i].w;
    }

    // --- dual GEMM, f32x2 over pixel pairs ---
    const int to = tid & 31;   // output channels o = to + 32*i
    const int tp = tid >> 5;   // pixel group: pixels tp*8 .. tp*8+7  (warp == tp)
    u64 aQ[8][4], aK[8][4];
#pragma unroll
    for (int i = 0; i < 8; i++) {
        float bq = b0[to + 32 * i], bk = b1[to + 32 * i];
        u64 bqp = pk2(bq, bq), bkp = pk2(bk, bk);
#pragma unroll
        for (int jp = 0; jp < 4; jp++) { aQ[i][jp] = bqp; aK[i][jp] = bkp; }
    }

    // prefetch tile 0 of the weights
    float r0[KT], r1[KT];
#pragma unroll
    for (int t = 0; t < KT; t++) {
        r0[t] = g_w0t[t * 256 + tid];
        r1[t] = g_w1t[t * 256 + tid];
    }

    for (int kb = 0; kb < C_; kb += KT) {
        __syncthreads();
#pragma unroll
        for (int t = 0; t < KT; t++) {
            w0s[t * 256 + tid] = r0[t];
            w1s[t * 256 + tid] = r1[t];
        }
        __syncthreads();
        if (kb + KT < C_) {
#pragma unroll
            for (int t = 0; t < KT; t++) {
                r0[t] = g_w0t[(kb + KT + t) * 256 + tid];
                r1[t] = g_w1t[(kb + KT + t) * 256 + tid];
            }
        }
#pragma unroll
        for (int kk = 0; kk < KT; kk++) {
            const u64* qrow = (const u64*)(qs + (kb + kk) * QSTR + tp * 8);
            const u64* xrow = (const u64*)(xs + (kb + kk) * QSTR + tp * 8);
            u64 qp[4], xp2[4];
#pragma unroll
            for (int jp = 0; jp < 4; jp++) { qp[jp] = qrow[jp]; xp2[jp] = xrow[jp]; }
#pragma unroll
            for (int i = 0; i < 8; i++) {
                float w0v = w0s[kk * 256 + to + 32 * i];
                float w1v = w1s[kk * 256 + to + 32 * i];
                u64 w0p = pk2(w0v, w0v);
                u64 w1p = pk2(w1v, w1v);
#pragma unroll
                for (int jp = 0; jp < 4; jp++) {
                    fma2(aQ[i][jp], w0p, qp[jp]);
                    fma2(aK[i][jp], w1p, xp2[jp]);
                }
            }
        }
    }

    // --- epilogue: 5 stats per pixel, warp reduction over the 32 'to' lanes ---
#pragma unroll
    for (int j = 0; j < 8; j++) {
        const int jp = j >> 1, hi = j & 1;
        float sq = 0.f, sk = 0.f, sqq = 0.f, skk = 0.f, sqk = 0.f;
#pragma unroll
        for (int i = 0; i < 8; i++) {
            float qlo, qhi, klo, khi;
            upk2(aQ[i][jp], qlo, qhi);
            upk2(aK[i][jp], klo, khi);
            float q = hi ? qhi : qlo;
            float k2 = hi ? khi : klo;
            sq += q; sk += k2;
            sqq = fmaf(q, q, sqq);
            skk = fmaf(k2, k2, skk);
            sqk = fmaf(q, k2, sqk);
        }
#pragma unroll
        for (int o = 16; o > 0; o >>= 1) {
            sq  += __shfl_xor_sync(0xffffffffu, sq,  o);
            sk  += __shfl_xor_sync(0xffffffffu, sk,  o);
            sqq += __shfl_xor_sync(0xffffffffu, sqq, o);
            skk += __shfl_xor_sync(0xffffffffu, skk, o);
            sqk += __shfl_xor_sync(0xffffffffu, sqk, o);
        }
        if (to == j) {
            const float inv = 1.f / 256.f;
            float num = sqk - sq * sk * inv;
            float dq  = sqq - sq * sq * inv + 1e-5f;
            float dk  = skk - sk * sk * inv + 1e-5f;
            out[base + tp * 8 + j] = num * rsqrtf(dq) * rsqrtf(dk);
        }
    }
}

// ---------------------------------------------------------------------------
extern "C" void kernel_launch(void* const* d_in, const int* in_sizes, int n_in,
                              void* d_out, int out_size) {
    const float* x      = (const float*)d_in[0];
    const float* offset = (const float*)d_in[1];
    const float* w0     = (const float*)d_in[2];
    const float* b0     = (const float*)d_in[3];
    const float* w1     = (const float*)d_in[4];
    const float* b1     = (const float*)d_in[5];
    float* out = (float*)d_out;

    k_tx<<<dim3(HW_ / 32, C_ / 32, B_), dim3(32, 8)>>>(x);
    k_tw<<<dim3(8, 8, 2), dim3(32, 8)>>>(w0, w1);

    size_t smem = (size_t)(C_ * QSTR * 2 + KT * 256 * 2 + 18 * PTILE) * sizeof(float);
    cudaFuncSetAttribute(k_main, cudaFuncAttributeMaxDynamicSharedMemorySize, (int)smem);
    k_main<<<NPIX_ / PTILE, 256, smem>>>(offset, b0, b1, out);
}

// round 4
// speedup vs baseline: 1.1212x; 1.0163x over previous
#include <cuda_runtime.h>
#include <math.h>

#define B_ 4
#define C_ 256
#define H_ 128
#define W_ 128
#define HW_ (H_*W_)
#define NPIX_ (B_*HW_)
#define PTILE 32
#define KT 8
#define QXSTR 66   // floats per channel row: 2*PTILE interleaved (q,x) + 2 pad

// Scratch: x transposed to NHWC, weights transposed to k-major.
__device__ float g_xt[(size_t)NPIX_ * C_];   // 64 MB
__device__ float g_w0t[C_ * C_];
__device__ float g_w1t[C_ * C_];

typedef unsigned long long u64;

__device__ __forceinline__ u64 pk2(float lo, float hi) {
    u64 r; asm("mov.b64 %0, {%1,%2};" : "=l"(r) : "f"(lo), "f"(hi)); return r;
}
__device__ __forceinline__ void upk2(u64 v, float& lo, float& hi) {
    asm("mov.b64 {%0,%1}, %2;" : "=f"(lo), "=f"(hi) : "l"(v));
}
__device__ __forceinline__ void fma2(u64& d, u64 a, u64 b) {
    asm("fma.rn.f32x2 %0, %1, %2, %0;" : "+l"(d) : "l"(a), "l"(b));
}

// ---------------------------------------------------------------------------
// Transpose x: [B][C][HW] -> g_xt [B][HW][C]
// ---------------------------------------------------------------------------
__global__ void k_tx(const float* __restrict__ x) {
    __shared__ float t[32][33];
    int b = blockIdx.z, s0 = blockIdx.x * 32, c0 = blockIdx.y * 32;
    int tx = threadIdx.x, ty = threadIdx.y;
    const float* xi = x + (size_t)b * C_ * HW_;
    float* xo = g_xt + (size_t)b * HW_ * C_;
#pragma unroll
    for (int i = 0; i < 32; i += 8)
        t[ty + i][tx] = xi[(size_t)(c0 + ty + i) * HW_ + s0 + tx];
    __syncthreads();
#pragma unroll
    for (int i = 0; i < 32; i += 8)
        xo[(size_t)(s0 + ty + i) * C_ + c0 + tx] = t[tx][ty + i];
}

// Transpose weights: w[o][c] -> wt[c][o]
__global__ void k_tw(const float* __restrict__ w0, const float* __restrict__ w1) {
    __shared__ float t[32][33];
    const float* wi = blockIdx.z ? w1 : w0;
    float* wo = blockIdx.z ? g_w1t : g_w0t;
    int o0 = blockIdx.y * 32, c0 = blockIdx.x * 32;
    int tx = threadIdx.x, ty = threadIdx.y;
#pragma unroll
    for (int i = 0; i < 32; i += 8)
        t[ty + i][tx] = wi[(o0 + ty + i) * C_ + c0 + tx];
    __syncthreads();
#pragma unroll
    for (int i = 0; i < 32; i += 8)
        wo[(c0 + ty + i) * C_ + o0 + tx] = t[tx][ty + i];
}

// ---------------------------------------------------------------------------
// Fused: deformable gather+max -> dual GEMM packed as f32x2 {Q,K} lanes
// Block: 256 threads, 32 consecutive pixels on one row. 2 CTAs/SM.
// ---------------------------------------------------------------------------
__global__ __launch_bounds__(256, 2)
void k_main(const float* __restrict__ offset, const float* __restrict__ b0,
            const float* __restrict__ b1, float* __restrict__ out) {
    extern __shared__ float sm[];
    float* qxs  = sm;                     // [C_][QXSTR]: (q,x) pairs per pixel
    float* ws   = qxs + C_ * QXSTR;       // [KT][512]: (w0,w1) pairs per out-ch
    float* offs = ws + KT * 512;          // [18][PTILE]

    const int tid  = threadIdx.x;
    const int base = blockIdx.x * PTILE;
    const int b    = base / HW_;
    const int rem  = base % HW_;
    const int y    = rem / W_;
    const int x0   = rem % W_;

    // offsets for the 32 pixels
    for (int i = tid; i < 18 * PTILE; i += 256) {
        int j = i >> 5, p = i & 31;
        offs[i] = offset[((size_t)b * 18 + j) * HW_ + y * W_ + x0 + p];
    }
    __syncthreads();

    const float* xtb = g_xt + (size_t)b * HW_ * C_;
    const int sub = tid & 7;      // 8 threads per pixel, 32 channels each (8 float4)
    const int p   = tid >> 3;
    const int pxi = x0 + p;

    // stage x (key input) into the hi lane: qxs[c][2p+1]
    {
        const float4* xp = (const float4*)(xtb + (size_t)(y * W_ + pxi) * C_);
#pragma unroll
        for (int i = 0; i < 8; i++) {
            float4 v = xp[sub + 8 * i];
            int c = 4 * (sub + 8 * i);
            qxs[(c + 0) * QXSTR + 2 * p + 1] = v.x;
            qxs[(c + 1) * QXSTR + 2 * p + 1] = v.y;
            qxs[(c + 2) * QXSTR + 2 * p + 1] = v.z;
            qxs[(c + 3) * QXSTR + 2 * p + 1] = v.w;
        }
    }

    // deformable 3x3 unfold fused with max over the 9 sample points
    float4 qm[8];
#pragma unroll
    for (int i = 0; i < 8; i++) { qm[i].x = qm[i].y = qm[i].z = qm[i].w = -3.4e38f; }

#pragma unroll
    for (int k = 0; k < 9; k++) {
        const int kh = k / 3 - 1, kw = k % 3 - 1;
        float py  = (float)(y + kh)   + offs[(2 * k) * PTILE + p];
        float pxx = (float)(pxi + kw) + offs[(2 * k + 1) * PTILE + p];
        float fy = floorf(py), fx = floorf(pxx);
        float wy = py - fy, wx = pxx - fx;
        int iy = (int)fy, ix = (int)fx;

        float4 acc[8];
#pragma unroll
        for (int i = 0; i < 8; i++) { acc[i].x = acc[i].y = acc[i].z = acc[i].w = 0.f; }

        float cw[4] = { (1.f - wy) * (1.f - wx), (1.f - wy) * wx,
                        wy * (1.f - wx),         wy * wx };
        int cy[4] = { iy, iy, iy + 1, iy + 1 };
        int cx[4] = { ix, ix + 1, ix, ix + 1 };
#pragma unroll
        for (int c4 = 0; c4 < 4; c4++) {
            if (cy[c4] >= 0 && cy[c4] < H_ && cx[c4] >= 0 && cx[c4] < W_) {
                const float4* cp = (const float4*)(xtb + (size_t)(cy[c4] * W_ + cx[c4]) * C_);
                float w = cw[c4];
#pragma unroll
                for (int i = 0; i < 8; i++) {
                    float4 v = cp[sub + 8 * i];
                    acc[i].x = fmaf(w, v.x, acc[i].x);
                    acc[i].y = fmaf(w, v.y, acc[i].y);
                    acc[i].z = fmaf(w, v.z, acc[i].z);
                    acc[i].w = fmaf(w, v.w, acc[i].w);
                }
            }
        }
#pragma unroll
        for (int i = 0; i < 8; i++) {
            qm[i].x = fmaxf(qm[i].x, acc[i].x);
            qm[i].y = fmaxf(qm[i].y, acc[i].y);
            qm[i].z = fmaxf(qm[i].z, acc[i].z);
            qm[i].w = fmaxf(qm[i].w, acc[i].w);
        }
    }
    // q into the lo lane: qxs[c][2p]
#pragma unroll
    for (int i = 0; i < 8; i++) {
        int c = 4 * (sub + 8 * i);
        qxs[(c + 0) * QXSTR + 2 * p] = qm[i].x;
        qxs[(c + 1) * QXSTR + 2 * p] = qm[i].y;
        qxs[(c + 2) * QXSTR + 2 * p] = qm[i].z;
        qxs[(c + 3) * QXSTR + 2 * p] = qm[i].w;
    }

    // --- dual GEMM: lanes of f32x2 carry {Q, K} ---
    const int to = tid & 31;   // output channels o = to + 32*i
    const int tp = tid >> 5;   // pixel group: pixels tp*4 .. tp*4+3 (warp == tp)
    u64 aQK[8][4];
#pragma unroll
    for (int i = 0; i < 8; i++) {
        u64 bb = pk2(b0[to + 32 * i], b1[to + 32 * i]);
#pragma unroll
        for (int j = 0; j < 4; j++) aQK[i][j] = bb;
    }

    // prefetch tile 0 of the weights
    float r0[KT], r1[KT];
#pragma unroll
    for (int t = 0; t < KT; t++) {
        r0[t] = g_w0t[t * 256 + tid];
        r1[t] = g_w1t[t * 256 + tid];
    }

    u64* ws_u = (u64*)ws;
    for (int kb = 0; kb < C_; kb += KT) {
        __syncthreads();
#pragma unroll
        for (int t = 0; t < KT; t++)
            ws_u[t * 256 + tid] = pk2(r0[t], r1[t]);
        __syncthreads();
        if (kb + KT < C_) {
#pragma unroll
            for (int t = 0; t < KT; t++) {
                r0[t] = g_w0t[(kb + KT + t) * 256 + tid];
                r1[t] = g_w1t[(kb + KT + t) * 256 + tid];
            }
        }
#pragma unroll
        for (int kk = 0; kk < KT; kk++) {
            const u64* qxrow = (const u64*)(qxs + (kb + kk) * QXSTR);
            u64 qx[4];
#pragma unroll
            for (int j = 0; j < 4; j++) qx[j] = qxrow[tp * 4 + j];
#pragma unroll
            for (int i = 0; i < 8; i++) {
                u64 w = ws_u[kk * 256 + to + 32 * i];
#pragma unroll
                for (int j = 0; j < 4; j++)
                    fma2(aQK[i][j], w, qx[j]);
            }
        }
    }

    // --- epilogue: 5 stats per pixel, warp reduction over the 32 'to' lanes ---
#pragma unroll
    for (int j = 0; j < 4; j++) {
        float sq = 0.f, sk = 0.f, sqq = 0.f, skk = 0.f, sqk = 0.f;
#pragma unroll
        for (int i = 0; i < 8; i++) {
            float q, k2;
            upk2(aQK[i][j], q, k2);
            sq += q; sk += k2;
            sqq = fmaf(q, q, sqq);
            skk = fmaf(k2, k2, skk);
            sqk = fmaf(q, k2, sqk);
        }
#pragma unroll
        for (int o = 16; o > 0; o >>= 1) {
            sq  += __shfl_xor_sync(0xffffffffu, sq,  o);
            sk  += __shfl_xor_sync(0xffffffffu, sk,  o);
            sqq += __shfl_xor_sync(0xffffffffu, sqq, o);
            skk += __shfl_xor_sync(0xffffffffu, skk, o);
            sqk += __shfl_xor_sync(0xffffffffu, sqk, o);
        }
        if (to == j) {
            const float inv = 1.f / 256.f;
            float num = sqk - sq * sk * inv;
            float dq  = sqq - sq * sq * inv + 1e-5f;
            float dk  = skk - sk * sk * inv + 1e-5f;
            out[base + tp * 4 + j] = num * rsqrtf(dq) * rsqrtf(dk);
        }
    }
}

// ---------------------------------------------------------------------------
extern "C" void kernel_launch(void* const* d_in, const int* in_sizes, int n_in,
                              void* d_out, int out_size) {
    const float* x      = (const float*)d_in[0];
    const float* offset = (const float*)d_in[1];
    const float* w0     = (const float*)d_in[2];
    const float* b0     = (const float*)d_in[3];
    const float* w1     = (const float*)d_in[4];
    const float* b1     = (const float*)d_in[5];
    float* out = (float*)d_out;

    k_tx<<<dim3(HW_ / 32, C_ / 32, B_), dim3(32, 8)>>>(x);
    k_tw<<<dim3(8, 8, 2), dim3(32, 8)>>>(w0, w1);

    size_t smem = (size_t)(C_ * QXSTR + KT * 512 + 18 * PTILE) * sizeof(float);
    cudaFuncSetAttribute(k_main, cudaFuncAttributeMaxDynamicSharedMemorySize, (int)smem);
    k_main<<<NPIX_ / PTILE, 256, smem>>>(offset, b0, b1, out);
}

// round 6
// speedup vs baseline: 1.2632x; 1.1266x over previous
#include <cuda_runtime.h>
#include <cuda_bf16.h>
#include <math.h>
#include <stdint.h>

#define B_ 4
#define C_ 256
#define H_ 128
#define W_ 128
#define HW_ (H_*W_)
#define NPIX_ (B_*HW_)
#define NTILE (NPIX_/128)    // 512 GEMM tiles, one per image row

typedef unsigned int u32;

// ---------------- global scratch ----------------
__device__ float g_xt[(size_t)NPIX_ * C_];                                  // 64 MB
__device__ __align__(16) __nv_bfloat16 gQ[(size_t)NTILE * 2 * 128 * 256];   // 64 MB (hi,lo planes)
__device__ __align__(16) __nv_bfloat16 gX[(size_t)NTILE * 2 * 128 * 256];   // 64 MB
__device__ __align__(16) __nv_bfloat16 gW[2 * 2 * 256 * 256];               // 512 KB

// ---------------------------------------------------------------------------
// Transpose x: [B][C][HW] -> g_xt [B][HW][C]
// ---------------------------------------------------------------------------
__global__ void k_tx(const float* __restrict__ x) {
    __shared__ float t[32][33];
    int b = blockIdx.z, s0 = blockIdx.x * 32, c0 = blockIdx.y * 32;
    int tx = threadIdx.x, ty = threadIdx.y;
    const float* xi = x + (size_t)b * C_ * HW_;
    float* xo = g_xt + (size_t)b * HW_ * C_;
#pragma unroll
    for (int i = 0; i < 32; i += 8)
        t[ty + i][tx] = xi[(size_t)(c0 + ty + i) * HW_ + s0 + tx];
    __syncthreads();
#pragma unroll
    for (int i = 0; i < 32; i += 8)
        xo[(size_t)(s0 + ty + i) * C_ + c0 + tx] = t[tx][ty + i];
}

// ---------------------------------------------------------------------------
// Weight prep: w[o][c] fp32 -> gW[g][plane][o][k] bf16 (hi/lo split)
// ---------------------------------------------------------------------------
__global__ void k_wprep(const float* __restrict__ w0, const float* __restrict__ w1) {
    int g = blockIdx.x;
    int o = threadIdx.x;
    const float* w = g ? w1 : w0;
    __nv_bfloat16* hi = gW + ((size_t)(g * 2 + 0) * 256 + o) * 256;
    __nv_bfloat16* lo = gW + ((size_t)(g * 2 + 1) * 256 + o) * 256;
    for (int k = 0; k < 256; k++) {
        float a = w[o * 256 + k];
        __nv_bfloat16 h = __float2bfloat16_rn(a);
        hi[k] = h;
        lo[k] = __float2bfloat16_rn(a - __bfloat162float(h));
    }
}

// ---------------------------------------------------------------------------
// Gather: deformable 3x3 max-unfold -> gQ ; copy x row -> gX (bf16 hi/lo)
// Block: 256 threads, 32 pixels (8 threads/pixel, 32 channels each)
// ---------------------------------------------------------------------------
__device__ __forceinline__ void split_store4(__nv_bfloat16* pHi, __nv_bfloat16* pLo, float4 v) {
    __nv_bfloat16 h0 = __float2bfloat16_rn(v.x), h1 = __float2bfloat16_rn(v.y);
    __nv_bfloat16 h2 = __float2bfloat16_rn(v.z), h3 = __float2bfloat16_rn(v.w);
    __nv_bfloat162 a = __halves2bfloat162(h0, h1), b = __halves2bfloat162(h2, h3);
    __nv_bfloat162 c = __halves2bfloat162(
        __float2bfloat16_rn(v.x - __bfloat162float(h0)),
        __float2bfloat16_rn(v.y - __bfloat162float(h1)));
    __nv_bfloat162 d = __halves2bfloat162(
        __float2bfloat16_rn(v.z - __bfloat162float(h2)),
        __float2bfloat16_rn(v.w - __bfloat162float(h3)));
    uint2 hv, lv;
    hv.x = *(u32*)&a; hv.y = *(u32*)&b;
    lv.x = *(u32*)&c; lv.y = *(u32*)&d;
    *(uint2*)pHi = hv;
    *(uint2*)pLo = lv;
}

__global__ __launch_bounds__(256)
void k_gather(const float* __restrict__ offset) {
    __shared__ float offs[18 * 32];
    const int tid  = threadIdx.x;
    const int base = blockIdx.x * 32;
    const int b    = base / HW_;
    const int rem  = base % HW_;
    const int y    = rem / W_;
    const int x0   = rem % W_;

    for (int i = tid; i < 18 * 32; i += 256) {
        int j = i >> 5, p = i & 31;
        offs[i] = offset[((size_t)b * 18 + j) * HW_ + y * W_ + x0 + p];
    }
    __syncthreads();

    const float* xtb = g_xt + (size_t)b * HW_ * C_;
    const int sub = tid & 7;
    const int p   = tid >> 3;
    const int pxi = x0 + p;
    const int tile = blockIdx.x >> 2;
    const int r    = ((blockIdx.x & 3) << 5) + p;

    float4 qm[8];
#pragma unroll
    for (int i = 0; i < 8; i++) { qm[i].x = qm[i].y = qm[i].z = qm[i].w = -3.4e38f; }

#pragma unroll
    for (int k = 0; k < 9; k++) {
        const int kh = k / 3 - 1, kw = k % 3 - 1;
        float py  = (float)(y + kh)   + offs[(2 * k) * 32 + p];
        float pxx = (float)(pxi + kw) + offs[(2 * k + 1) * 32 + p];
        float fy = floorf(py), fx = floorf(pxx);
        float wy = py - fy, wx = pxx - fx;
        int iy = (int)fy, ix = (int)fx;

        float4 acc[8];
#pragma unroll
        for (int i = 0; i < 8; i++) { acc[i].x = acc[i].y = acc[i].z = acc[i].w = 0.f; }

        float cw[4] = { (1.f - wy) * (1.f - wx), (1.f - wy) * wx,
                        wy * (1.f - wx),         wy * wx };
        int cy[4] = { iy, iy, iy + 1, iy + 1 };
        int cx[4] = { ix, ix + 1, ix, ix + 1 };
#pragma unroll
        for (int c4 = 0; c4 < 4; c4++) {
            if (cy[c4] >= 0 && cy[c4] < H_ && cx[c4] >= 0 && cx[c4] < W_) {
                const float4* cp = (const float4*)(xtb + (size_t)(cy[c4] * W_ + cx[c4]) * C_);
                float w = cw[c4];
#pragma unroll
                for (int i = 0; i < 8; i++) {
                    float4 v = cp[sub + 8 * i];
                    acc[i].x = fmaf(w, v.x, acc[i].x);
                    acc[i].y = fmaf(w, v.y, acc[i].y);
                    acc[i].z = fmaf(w, v.z, acc[i].z);
                    acc[i].w = fmaf(w, v.w, acc[i].w);
                }
            }
        }
#pragma unroll
        for (int i = 0; i < 8; i++) {
            qm[i].x = fmaxf(qm[i].x, acc[i].x);
            qm[i].y = fmaxf(qm[i].y, acc[i].y);
            qm[i].z = fmaxf(qm[i].z, acc[i].z);
            qm[i].w = fmaxf(qm[i].w, acc[i].w);
        }
    }

    // write q tiles: gQ[tile][plane][r][c]
    size_t tbase = (size_t)tile * 65536 + (size_t)r * 256;
#pragma unroll
    for (int i = 0; i < 8; i++) {
        int c = 4 * (sub + 8 * i);
        split_store4(gQ + tbase + c, gQ + tbase + 32768 + c, qm[i]);
    }
    // write x tiles
    const float4* xp = (const float4*)(xtb + (size_t)(y * W_ + pxi) * C_);
#pragma unroll
    for (int i = 0; i < 8; i++) {
        float4 v = xp[sub + 8 * i];
        int c = 4 * (sub + 8 * i);
        split_store4(gX + tbase + c, gX + tbase + 32768 + c, v);
    }
}

// ---------------------------------------------------------------------------
// GEMM via mma.sync bf16 (split-precision, 3 passes) + stats epilogue.
// One CTA (512 threads, 16 warps 4m x 4n) per 128-pixel tile.
// ---------------------------------------------------------------------------
__device__ __forceinline__ void mma_bf16(float* d, u32 a0, u32 a1, u32 a2, u32 a3,
                                         u32 b0, u32 b1) {
    asm volatile(
        "mma.sync.aligned.m16n8k16.row.col.f32.bf16.bf16.f32 "
        "{%0,%1,%2,%3},{%4,%5,%6,%7},{%8,%9},{%0,%1,%2,%3};"
        : "+f"(d[0]), "+f"(d[1]), "+f"(d[2]), "+f"(d[3])
        : "r"(a0), "r"(a1), "r"(a2), "r"(a3), "r"(b0), "r"(b1));
}

#define ARS 48        // padded row stride (bytes) for A/B staging
#define QPS 260       // qpark row stride (floats)
#define SOFF_BIAS  0
#define SOFF_STATS 2048
#define SOFF_A     12288   // [2 buf][2 plane][128][48B] = 24576
#define SOFF_B     36864   // [2 buf][2 plane][256][48B] = 49152
#define SOFF_QP    86016   // [128][260] f32 = 133120
#define SMEM_TOTAL 219136

__global__ __launch_bounds__(512, 1)
void k_gemm(const float* __restrict__ gb0, const float* __restrict__ gb1,
            float* __restrict__ out) {
    extern __shared__ unsigned char sm[];
    float* bias  = (float*)(sm + SOFF_BIAS);     // [512]
    float* stats = (float*)(sm + SOFF_STATS);    // [4 nw][5][128]
    unsigned char* smA = sm + SOFF_A;
    unsigned char* smB = sm + SOFF_B;
    float* qpark = (float*)(sm + SOFF_QP);

    const int tid = threadIdx.x, lane = tid & 31, wid = tid >> 5;
    const int mw = wid >> 2, nw = wid & 3;
    const int tile = blockIdx.x;

    if (tid < 256) { bias[tid] = gb0[tid]; bias[256 + tid] = gb1[tid]; }
    for (int i = tid; i < 4 * 5 * 128; i += 512) stats[i] = 0.f;

    // staging decomposition for A: 512 items = 128 rows x 2 planes x 2 halves
    const int sAr = tid >> 2, sApl = (tid >> 1) & 1, sAh = tid & 1;
    const int kq = (lane & 3) * 4;

    for (int ph = 0; ph < 2; ph++) {
        const __nv_bfloat16* Ab = (ph ? gX : gQ) + (size_t)tile * 65536;
        const __nv_bfloat16* Bb = gW + (size_t)ph * 131072;

        float acc[2][8][4];
#pragma unroll
        for (int s = 0; s < 2; s++)
#pragma unroll
            for (int t = 0; t < 8; t++)
#pragma unroll
                for (int j = 0; j < 4; j++) acc[s][t][j] = 0.f;

        // prologue: stage slice 0 into buf 0
        *(uint4*)(smA + sApl * 6144 + sAr * ARS + sAh * 16) =
            *(const uint4*)(Ab + sApl * 32768 + sAr * 256 + sAh * 8);
#pragma unroll
        for (int i = 0; i < 2; i++) {
            int idx = tid + i * 512;
            int n = idx >> 2, pl = (idx >> 1) & 1, hf = idx & 1;
            *(uint4*)(smB + pl * 12288 + n * ARS + hf * 16) =
                *(const uint4*)(Bb + pl * 65536 + n * 256 + hf * 8);
        }
        __syncthreads();

        for (int ks = 0; ks < 16; ks++) {
            const int cur = ks & 1;
            uint4 ra, rb0, rb1;
            if (ks < 15) {
                ra = *(const uint4*)(Ab + sApl * 32768 + sAr * 256 + (ks + 1) * 16 + sAh * 8);
                {
                    int idx = tid, n = idx >> 2, pl = (idx >> 1) & 1, hf = idx & 1;
                    rb0 = *(const uint4*)(Bb + pl * 65536 + n * 256 + (ks + 1) * 16 + hf * 8);
                }
                {
                    int idx = tid + 512, n = idx >> 2, pl = (idx >> 1) & 1, hf = idx & 1;
                    rb1 = *(const uint4*)(Bb + pl * 65536 + n * 256 + (ks + 1) * 16 + hf * 8);
                }
            }
            const unsigned char* Ac = smA + cur * 12288;
            const unsigned char* Bc = smB + cur * 24576;
            u32 ah[2][4], al[2][4];
#pragma unroll
            for (int s = 0; s < 2; s++) {
                int r1 = mw * 32 + s * 16 + (lane >> 2);
                const unsigned char* p0 = Ac + r1 * ARS + kq;
                ah[s][0] = *(const u32*)(p0);
                ah[s][1] = *(const u32*)(p0 + 8 * ARS);
                ah[s][2] = *(const u32*)(p0 + 16);
                ah[s][3] = *(const u32*)(p0 + 8 * ARS + 16);
                const unsigned char* p1 = p0 + 6144;
                al[s][0] = *(const u32*)(p1);
                al[s][1] = *(const u32*)(p1 + 8 * ARS);
                al[s][2] = *(const u32*)(p1 + 16);
                al[s][3] = *(const u32*)(p1 + 8 * ARS + 16);
            }
#pragma unroll
            for (int t = 0; t < 8; t++) {
                int n = nw * 64 + t * 8 + (lane >> 2);
                const unsigned char* pb = Bc + n * ARS + kq;
                u32 bh0 = *(const u32*)pb, bh1 = *(const u32*)(pb + 16);
                u32 bl0 = *(const u32*)(pb + 12288), bl1 = *(const u32*)(pb + 12288 + 16);
#pragma unroll
                for (int s = 0; s < 2; s++) {
                    mma_bf16(acc[s][t], ah[s][0], ah[s][1], ah[s][2], ah[s][3], bh0, bh1);
                    mma_bf16(acc[s][t], ah[s][0], ah[s][1], ah[s][2], ah[s][3], bl0, bl1);
                    mma_bf16(acc[s][t], al[s][0], al[s][1], al[s][2], al[s][3], bh0, bh1);
                }
            }
            if (ks < 15) {
                int nxt = cur ^ 1;
                *(uint4*)(smA + nxt * 12288 + sApl * 6144 + sAr * ARS + sAh * 16) = ra;
                {
                    int idx = tid, n = idx >> 2, pl = (idx >> 1) & 1, hf = idx & 1;
                    *(uint4*)(smB + nxt * 24576 + pl * 12288 + n * ARS + hf * 16) = rb0;
                }
                {
                    int idx = tid + 512, n = idx >> 2, pl = (idx >> 1) & 1, hf = idx & 1;
                    *(uint4*)(smB + nxt * 24576 + pl * 12288 + n * ARS + hf * 16) = rb1;
                }
            }
            __syncthreads();
        }

        if (ph == 0) {
            // park Q (+bias) in smem; same thread re-reads it in phase 1
#pragma unroll
            for (int s = 0; s < 2; s++) {
                int r1 = mw * 32 + s * 16 + (lane >> 2);
#pragma unroll
                for (int t = 0; t < 8; t++) {
                    int n0 = nw * 64 + t * 8 + (lane & 3) * 2;
                    float2 v0 = make_float2(acc[s][t][0] + bias[n0], acc[s][t][1] + bias[n0 + 1]);
                    float2 v1 = make_float2(acc[s][t][2] + bias[n0], acc[s][t][3] + bias[n0 + 1]);
                    *(float2*)(qpark + r1 * QPS + n0) = v0;
                    *(float2*)(qpark + (r1 + 8) * QPS + n0) = v1;
                }
            }
            __syncthreads();
        } else {
            // fold the 5 per-pixel stats
#pragma unroll
            for (int s = 0; s < 2; s++) {
                int r1 = mw * 32 + s * 16 + (lane >> 2);
                float st0[5] = {0, 0, 0, 0, 0}, st1[5] = {0, 0, 0, 0, 0};
#pragma unroll
                for (int t = 0; t < 8; t++) {
                    int n0 = nw * 64 + t * 8 + (lane & 3) * 2;
                    float bk0 = bias[256 + n0], bk1 = bias[256 + n0 + 1];
                    float2 q0 = *(float2*)(qpark + r1 * QPS + n0);
                    float2 q1 = *(float2*)(qpark + (r1 + 8) * QPS + n0);
                    float k0v = acc[s][t][0] + bk0, k1v = acc[s][t][1] + bk1;
                    float k2v = acc[s][t][2] + bk0, k3v = acc[s][t][3] + bk1;
                    st0[0] += q0.x + q0.y;  st0[1] += k0v + k1v;
                    st0[2] = fmaf(q0.x, q0.x, fmaf(q0.y, q0.y, st0[2]));
                    st0[3] = fmaf(k0v, k0v, fmaf(k1v, k1v, st0[3]));
                    st0[4] = fmaf(q0.x, k0v, fmaf(q0.y, k1v, st0[4]));
                    st1[0] += q1.x + q1.y;  st1[1] += k2v + k3v;
                    st1[2] = fmaf(q1.x, q1.x, fmaf(q1.y, q1.y, st1[2]));
                    st1[3] = fmaf(k2v, k2v, fmaf(k3v, k3v, st1[3]));
                    st1[4] = fmaf(q1.x, k2v, fmaf(q1.y, k3v, st1[4]));
                }
#pragma unroll
                for (int j = 0; j < 5; j++) {
                    st0[j] += __shfl_xor_sync(0xffffffffu, st0[j], 1);
                    st0[j] += __shfl_xor_sync(0xffffffffu, st0[j], 2);
                    st1[j] += __shfl_xor_sync(0xffffffffu, st1[j], 1);
                    st1[j] += __shfl_xor_sync(0xffffffffu, st1[j], 2);
                }
                if ((lane & 3) == 0) {
#pragma unroll
                    for (int j = 0; j < 5; j++) {
                        stats[(nw * 5 + j) * 128 + r1]     = st0[j];
                        stats[(nw * 5 + j) * 128 + r1 + 8] = st1[j];
                    }
                }
            }
            __syncthreads();
            if (tid < 128) {
                float sq = 0, sk = 0, sqq = 0, skk = 0, sqk = 0;
#pragma unroll
                for (int w = 0; w < 4; w++) {
                    sq  += stats[(w * 5 + 0) * 128 + tid];
                    sk  += stats[(w * 5 + 1) * 128 + tid];
                    sqq += stats[(w * 5 + 2) * 128 + tid];
                    skk += stats[(w * 5 + 3) * 128 + tid];
                    sqk += stats[(w * 5 + 4) * 128 + tid];
                }
                const float inv = 1.f / 256.f;
                float num = sqk - sq * sk * inv;
                float dq  = sqq - sq * sq * inv + 1e-5f;
                float dk  = skk - sk * sk * inv + 1e-5f;
                out[tile * 128 + tid] = num * rsqrtf(dq) * rsqrtf(dk);
            }
        }
    }
}

// ---------------------------------------------------------------------------
extern "C" void kernel_launch(void* const* d_in, const int* in_sizes, int n_in,
                              void* d_out, int out_size) {
    const float* x      = (const float*)d_in[0];
    const float* offset = (const float*)d_in[1];
    const float* w0     = (const float*)d_in[2];
    const float* b0     = (const float*)d_in[3];
    const float* w1     = (const float*)d_in[4];
    const float* b1     = (const float*)d_in[5];
    float* out = (float*)d_out;

    k_tx<<<dim3(HW_ / 32, C_ / 32, B_), dim3(32, 8)>>>(x);
    k_wprep<<<2, 256>>>(w0, w1);
    k_gather<<<NPIX_ / 32, 256>>>(offset);

    cudaFuncSetAttribute(k_gemm, cudaFuncAttributeMaxDynamicSharedMemorySize, SMEM_TOTAL);
    k_gemm<<<NTILE, 512, SMEM_TOTAL>>>(b0, b1, out);
}

// round 7
// speedup vs baseline: 1.4095x; 1.1158x over previous
#include <cuda_runtime.h>
#include <cuda_bf16.h>
#include <math.h>
#include <stdint.h>

#define B_ 4
#define C_ 256
#define H_ 128
#define W_ 128
#define HW_ (H_*W_)
#define NPIX_ (B_*HW_)
#define NTILE (NPIX_/128)    // 512 GEMM tiles, one per image row

typedef unsigned int u32;

// ---------------- global scratch ----------------
__device__ float g_xt[(size_t)NPIX_ * C_];                                  // 64 MB
__device__ __align__(16) __nv_bfloat16 gQ[(size_t)NTILE * 2 * 128 * 256];   // 64 MB (hi,lo planes)
__device__ __align__(16) __nv_bfloat16 gX[(size_t)NTILE * 2 * 128 * 256];   // 64 MB
__device__ __align__(16) __nv_bfloat16 gW[2 * 2 * 256 * 256];               // 512 KB

// ---------------- PTX helpers ----------------
__device__ __forceinline__ u32 smem_u32(const void* p) {
    u32 a; asm("{ .reg .u64 t; cvta.to.shared.u64 t, %1; cvt.u32.u64 %0, t; }"
               : "=r"(a) : "l"(p));
    return a;
}
__device__ __forceinline__ void ldmx4(u32 addr, u32* r) {
    asm volatile("ldmatrix.sync.aligned.m8n8.x4.shared.b16 {%0,%1,%2,%3}, [%4];"
                 : "=r"(r[0]), "=r"(r[1]), "=r"(r[2]), "=r"(r[3]) : "r"(addr));
}
__device__ __forceinline__ void cpa16(u32 dst, const void* src) {
    asm volatile("cp.async.cg.shared.global [%0], [%1], 16;" :: "r"(dst), "l"(src));
}
#define CP_COMMIT() asm volatile("cp.async.commit_group;" ::: "memory")
#define CP_WAIT(n)  asm volatile("cp.async.wait_group %0;" :: "n"(n) : "memory")

__device__ __forceinline__ void mma_bf16(float* d, const u32* a, u32 b0, u32 b1) {
    asm volatile(
        "mma.sync.aligned.m16n8k16.row.col.f32.bf16.bf16.f32 "
        "{%0,%1,%2,%3},{%4,%5,%6,%7},{%8,%9},{%0,%1,%2,%3};"
        : "+f"(d[0]), "+f"(d[1]), "+f"(d[2]), "+f"(d[3])
        : "r"(a[0]), "r"(a[1]), "r"(a[2]), "r"(a[3]), "r"(b0), "r"(b1));
}

// ---------------------------------------------------------------------------
// Transpose x: [B][C][HW] -> g_xt [B][HW][C]
// ---------------------------------------------------------------------------
__global__ void k_tx(const float* __restrict__ x) {
    __shared__ float t[32][33];
    int b = blockIdx.z, s0 = blockIdx.x * 32, c0 = blockIdx.y * 32;
    int tx = threadIdx.x, ty = threadIdx.y;
    const float* xi = x + (size_t)b * C_ * HW_;
    float* xo = g_xt + (size_t)b * HW_ * C_;
#pragma unroll
    for (int i = 0; i < 32; i += 8)
        t[ty + i][tx] = xi[(size_t)(c0 + ty + i) * HW_ + s0 + tx];
    __syncthreads();
#pragma unroll
    for (int i = 0; i < 32; i += 8)
        xo[(size_t)(s0 + ty + i) * C_ + c0 + tx] = t[tx][ty + i];
}

// ---------------------------------------------------------------------------
// Weight prep: w[o][c] fp32 -> gW[g][plane][o][k] bf16 (hi/lo split)
// ---------------------------------------------------------------------------
__global__ void k_wprep(const float* __restrict__ w0, const float* __restrict__ w1) {
    int g = blockIdx.x;
    int o = threadIdx.x;
    const float* w = g ? w1 : w0;
    __nv_bfloat16* hi = gW + ((size_t)(g * 2 + 0) * 256 + o) * 256;
    __nv_bfloat16* lo = gW + ((size_t)(g * 2 + 1) * 256 + o) * 256;
    for (int k = 0; k < 256; k++) {
        float a = w[o * 256 + k];
        __nv_bfloat16 h = __float2bfloat16_rn(a);
        hi[k] = h;
        lo[k] = __float2bfloat16_rn(a - __bfloat162float(h));
    }
}

// ---------------------------------------------------------------------------
// Gather: deformable 3x3 max-unfold -> gQ ; copy x row -> gX (bf16 hi/lo)
// ---------------------------------------------------------------------------
__device__ __forceinline__ void split_store4(__nv_bfloat16* pHi, __nv_bfloat16* pLo, float4 v) {
    __nv_bfloat16 h0 = __float2bfloat16_rn(v.x), h1 = __float2bfloat16_rn(v.y);
    __nv_bfloat16 h2 = __float2bfloat16_rn(v.z), h3 = __float2bfloat16_rn(v.w);
    __nv_bfloat162 a = __halves2bfloat162(h0, h1), b = __halves2bfloat162(h2, h3);
    __nv_bfloat162 c = __halves2bfloat162(
        __float2bfloat16_rn(v.x - __bfloat162float(h0)),
        __float2bfloat16_rn(v.y - __bfloat162float(h1)));
    __nv_bfloat162 d = __halves2bfloat162(
        __float2bfloat16_rn(v.z - __bfloat162float(h2)),
        __float2bfloat16_rn(v.w - __bfloat162float(h3)));
    uint2 hv, lv;
    hv.x = *(u32*)&a; hv.y = *(u32*)&b;
    lv.x = *(u32*)&c; lv.y = *(u32*)&d;
    *(uint2*)pHi = hv;
    *(uint2*)pLo = lv;
}

__global__ __launch_bounds__(256)
void k_gather(const float* __restrict__ offset) {
    __shared__ float offs[18 * 32];
    const int tid  = threadIdx.x;
    const int base = blockIdx.x * 32;
    const int b    = base / HW_;
    const int rem  = base % HW_;
    const int y    = rem / W_;
    const int x0   = rem % W_;

    for (int i = tid; i < 18 * 32; i += 256) {
        int j = i >> 5, p = i & 31;
        offs[i] = offset[((size_t)b * 18 + j) * HW_ + y * W_ + x0 + p];
    }
    __syncthreads();

    const float* xtb = g_xt + (size_t)b * HW_ * C_;
    const int sub = tid & 7;
    const int p   = tid >> 3;
    const int pxi = x0 + p;
    const int tile = blockIdx.x >> 2;
    const int r    = ((blockIdx.x & 3) << 5) + p;

    float4 qm[8];
#pragma unroll
    for (int i = 0; i < 8; i++) { qm[i].x = qm[i].y = qm[i].z = qm[i].w = -3.4e38f; }

#pragma unroll
    for (int k = 0; k < 9; k++) {
        const int kh = k / 3 - 1, kw = k % 3 - 1;
        float py  = (float)(y + kh)   + offs[(2 * k) * 32 + p];
        float pxx = (float)(pxi + kw) + offs[(2 * k + 1) * 32 + p];
        float fy = floorf(py), fx = floorf(pxx);
        float wy = py - fy, wx = pxx - fx;
        int iy = (int)fy, ix = (int)fx;

        float4 acc[8];
#pragma unroll
        for (int i = 0; i < 8; i++) { acc[i].x = acc[i].y = acc[i].z = acc[i].w = 0.f; }

        float cw[4] = { (1.f - wy) * (1.f - wx), (1.f - wy) * wx,
                        wy * (1.f - wx),         wy * wx };
        int cy[4] = { iy, iy, iy + 1, iy + 1 };
        int cx[4] = { ix, ix + 1, ix, ix + 1 };
#pragma unroll
        for (int c4 = 0; c4 < 4; c4++) {
            if (cy[c4] >= 0 && cy[c4] < H_ && cx[c4] >= 0 && cx[c4] < W_) {
                const float4* cp = (const float4*)(xtb + (size_t)(cy[c4] * W_ + cx[c4]) * C_);
                float w = cw[c4];
#pragma unroll
                for (int i = 0; i < 8; i++) {
                    float4 v = cp[sub + 8 * i];
                    acc[i].x = fmaf(w, v.x, acc[i].x);
                    acc[i].y = fmaf(w, v.y, acc[i].y);
                    acc[i].z = fmaf(w, v.z, acc[i].z);
                    acc[i].w = fmaf(w, v.w, acc[i].w);
                }
            }
        }
#pragma unroll
        for (int i = 0; i < 8; i++) {
            qm[i].x = fmaxf(qm[i].x, acc[i].x);
            qm[i].y = fmaxf(qm[i].y, acc[i].y);
            qm[i].z = fmaxf(qm[i].z, acc[i].z);
            qm[i].w = fmaxf(qm[i].w, acc[i].w);
        }
    }

    size_t tbase = (size_t)tile * 65536 + (size_t)r * 256;
#pragma unroll
    for (int i = 0; i < 8; i++) {
        int c = 4 * (sub + 8 * i);
        split_store4(gQ + tbase + c, gQ + tbase + 32768 + c, qm[i]);
    }
    const float4* xp = (const float4*)(xtb + (size_t)(y * W_ + pxi) * C_);
#pragma unroll
    for (int i = 0; i < 8; i++) {
        float4 v = xp[sub + 8 * i];
        int c = 4 * (sub + 8 * i);
        split_store4(gX + tbase + c, gX + tbase + 32768 + c, v);
    }
}

// ---------------------------------------------------------------------------
// GEMM via mma.sync bf16 (split-precision, 3 terms) + stats epilogue.
// One CTA (512 threads, 16 warps 4m x 4n) per 128-pixel tile.
// cp.async double-buffered staging + ldmatrix fragment loads.
// ---------------------------------------------------------------------------
#define ARS 48        // padded row stride (bytes) for A/B staging
#define QPS 260       // qpark row stride (floats)
#define SOFF_BIAS  0
#define SOFF_STATS 2048
#define SOFF_A     12288   // [2 buf][2 plane][128][48B] = 24576
#define SOFF_B     36864   // [2 buf][2 plane][256][48B] = 49152
#define SOFF_QP    86016   // [128][260] f32 = 133120
#define SMEM_TOTAL 219136

__global__ __launch_bounds__(512, 1)
void k_gemm(const float* __restrict__ gb0, const float* __restrict__ gb1,
            float* __restrict__ out) {
    extern __shared__ unsigned char sm[];
    float* bias  = (float*)(sm + SOFF_BIAS);     // [512]
    float* stats = (float*)(sm + SOFF_STATS);    // [4 nw][5][128]
    float* qpark = (float*)(sm + SOFF_QP);
    const u32 smb = smem_u32(sm);
    const u32 smA = smb + SOFF_A;
    const u32 smB = smb + SOFF_B;

    const int tid = threadIdx.x, lane = tid & 31, wid = tid >> 5;
    const int mw = wid >> 2, nw = wid & 3;
    const int tile = blockIdx.x;

    if (tid < 256) { bias[tid] = gb0[tid]; bias[256 + tid] = gb1[tid]; }
    for (int i = tid; i < 4 * 5 * 128; i += 512) stats[i] = 0.f;

    // staging decomposition: A 512 x 16B chunks, B 1024 x 16B chunks
    const int aPl = tid >> 8, aRow = (tid >> 1) & 127, aHf = tid & 1;
    const int bRow = (tid >> 1) & 255, bHf = tid & 1;
    const u32 aDst0 = smA + aPl * 6144 + aRow * ARS + aHf * 16;
    const u32 bDst0 = smB + bRow * ARS + bHf * 16;

    // ldmatrix lane addressing
    const int aLRow = lane & 15, aLCol = (lane >> 4) * 16;
    const int bLRow = ((lane >> 4) << 3) + (lane & 7), bLCol = ((lane >> 3) & 1) * 16;

    for (int ph = 0; ph < 2; ph++) {
        const __nv_bfloat16* Ab = (ph ? gX : gQ) + (size_t)tile * 65536;
        const __nv_bfloat16* Bb = gW + (size_t)ph * 131072;
        const __nv_bfloat16* aSrc = Ab + aPl * 32768 + aRow * 256 + aHf * 8;
        const __nv_bfloat16* bSrc0 = Bb + bRow * 256 + bHf * 8;
        const __nv_bfloat16* bSrc1 = Bb + 65536 + bRow * 256 + bHf * 8;

        float acc[2][8][4];
#pragma unroll
        for (int s = 0; s < 2; s++)
#pragma unroll
            for (int t = 0; t < 8; t++)
#pragma unroll
                for (int j = 0; j < 4; j++) acc[s][t][j] = 0.f;

        // prologue: stage slice 0 into buf 0
        cpa16(aDst0, aSrc);
        cpa16(bDst0, bSrc0);
        cpa16(bDst0 + 12288, bSrc1);
        CP_COMMIT();

        for (int ks = 0; ks < 16; ks++) {
            const int cur = ks & 1;
            if (ks < 15) {
                const int nxt = cur ^ 1;
                cpa16(aDst0 + nxt * 12288, aSrc + (ks + 1) * 16);
                cpa16(bDst0 + nxt * 24576, bSrc0 + (ks + 1) * 16);
                cpa16(bDst0 + nxt * 24576 + 12288, bSrc1 + (ks + 1) * 16);
                CP_COMMIT();
                CP_WAIT(1);
            } else {
                CP_WAIT(0);
            }
            __syncthreads();

            const u32 Ac = smA + cur * 12288;
            const u32 Bc = smB + cur * 24576;

            u32 ah[2][4], al[2][4];
#pragma unroll
            for (int s = 0; s < 2; s++) {
                u32 arow = (u32)(mw * 32 + s * 16 + aLRow);
                ldmx4(Ac + arow * ARS + aLCol, ah[s]);
                ldmx4(Ac + 6144 + arow * ARS + aLCol, al[s]);
            }
#pragma unroll
            for (int tt = 0; tt < 4; tt++) {
                u32 brow = (u32)(nw * 64 + tt * 16 + bLRow);
                u32 bh[4], bl[4];
                ldmx4(Bc + brow * ARS + bLCol, bh);
                ldmx4(Bc + 12288 + brow * ARS + bLCol, bl);
#pragma unroll
                for (int half = 0; half < 2; half++) {
                    int t = tt * 2 + half;
                    u32 b0h = bh[half * 2], b1h = bh[half * 2 + 1];
                    u32 b0l = bl[half * 2], b1l = bl[half * 2 + 1];
#pragma unroll
                    for (int s = 0; s < 2; s++) {
                        mma_bf16(acc[s][t], ah[s], b0h, b1h);
                        mma_bf16(acc[s][t], ah[s], b0l, b1l);
                        mma_bf16(acc[s][t], al[s], b0h, b1h);
                    }
                }
            }
            __syncthreads();
        }

        if (ph == 0) {
            // park Q (+bias) in smem
#pragma unroll
            for (int s = 0; s < 2; s++) {
                int r1 = mw * 32 + s * 16 + (lane >> 2);
#pragma unroll
                for (int t = 0; t < 8; t++) {
                    int n0 = nw * 64 + t * 8 + (lane & 3) * 2;
                    float2 v0 = make_float2(acc[s][t][0] + bias[n0], acc[s][t][1] + bias[n0 + 1]);
                    float2 v1 = make_float2(acc[s][t][2] + bias[n0], acc[s][t][3] + bias[n0 + 1]);
                    *(float2*)(qpark + r1 * QPS + n0) = v0;
                    *(float2*)(qpark + (r1 + 8) * QPS + n0) = v1;
                }
            }
            __syncthreads();
        } else {
            // fold the 5 per-pixel stats
#pragma unroll
            for (int s = 0; s < 2; s++) {
                int r1 = mw * 32 + s * 16 + (lane >> 2);
                float st0[5] = {0, 0, 0, 0, 0}, st1[5] = {0, 0, 0, 0, 0};
#pragma unroll
                for (int t = 0; t < 8; t++) {
                    int n0 = nw * 64 + t * 8 + (lane & 3) * 2;
                    float bk0 = bias[256 + n0], bk1 = bias[256 + n0 + 1];
                    float2 q0 = *(float2*)(qpark + r1 * QPS + n0);
                    float2 q1 = *(float2*)(qpark + (r1 + 8) * QPS + n0);
                    float k0v = acc[s][t][0] + bk0, k1v = acc[s][t][1] + bk1;
                    float k2v = acc[s][t][2] + bk0, k3v = acc[s][t][3] + bk1;
                    st0[0] += q0.x + q0.y;  st0[1] += k0v + k1v;
                    st0[2] = fmaf(q0.x, q0.x, fmaf(q0.y, q0.y, st0[2]));
                    st0[3] = fmaf(k0v, k0v, fmaf(k1v, k1v, st0[3]));
                    st0[4] = fmaf(q0.x, k0v, fmaf(q0.y, k1v, st0[4]));
                    st1[0] += q1.x + q1.y;  st1[1] += k2v + k3v;
                    st1[2] = fmaf(q1.x, q1.x, fmaf(q1.y, q1.y, st1[2]));
                    st1[3] = fmaf(k2v, k2v, fmaf(k3v, k3v, st1[3]));
                    st1[4] = fmaf(q1.x, k2v, fmaf(q1.y, k3v, st1[4]));
                }
#pragma unroll
                for (int j = 0; j < 5; j++) {
                    st0[j] += __shfl_xor_sync(0xffffffffu, st0[j], 1);
                    st0[j] += __shfl_xor_sync(0xffffffffu, st0[j], 2);
                    st1[j] += __shfl_xor_sync(0xffffffffu, st1[j], 1);
                    st1[j] += __shfl_xor_sync(0xffffffffu, st1[j], 2);
                }
                if ((lane & 3) == 0) {
#pragma unroll
                    for (int j = 0; j < 5; j++) {
                        stats[(nw * 5 + j) * 128 + r1]     = st0[j];
                        stats[(nw * 5 + j) * 128 + r1 + 8] = st1[j];
                    }
                }
            }
            __syncthreads();
            if (tid < 128) {
                float sq = 0, sk = 0, sqq = 0, skk = 0, sqk = 0;
#pragma unroll
                for (int w = 0; w < 4; w++) {
                    sq  += stats[(w * 5 + 0) * 128 + tid];
                    sk  += stats[(w * 5 + 1) * 128 + tid];
                    sqq += stats[(w * 5 + 2) * 128 + tid];
                    skk += stats[(w * 5 + 3) * 128 + tid];
                    sqk += stats[(w * 5 + 4) * 128 + tid];
                }
                const float inv = 1.f / 256.f;
                float num = sqk - sq * sk * inv;
                float dq  = sqq - sq * sq * inv + 1e-5f;
                float dk  = skk - sk * sk * inv + 1e-5f;
                out[tile * 128 + tid] = num * rsqrtf(dq) * rsqrtf(dk);
            }
        }
    }
}

// ---------------------------------------------------------------------------
extern "C" void kernel_launch(void* const* d_in, const int* in_sizes, int n_in,
                              void* d_out, int out_size) {
    const float* x      = (const float*)d_in[0];
    const float* offset = (const float*)d_in[1];
    const float* w0     = (const float*)d_in[2];
    const float* b0     = (const float*)d_in[3];
    const float* w1     = (const float*)d_in[4];
    const float* b1     = (const float*)d_in[5];
    float* out = (float*)d_out;

    k_tx<<<dim3(HW_ / 32, C_ / 32, B_), dim3(32, 8)>>>(x);
    k_wprep<<<2, 256>>>(w0, w1);
    k_gather<<<NPIX_ / 32, 256>>>(offset);

    cudaFuncSetAttribute(k_gemm, cudaFuncAttributeMaxDynamicSharedMemorySize, SMEM_TOTAL);
    k_gemm<<<NTILE, 512, SMEM_TOTAL>>>(b0, b1, out);
}

// round 8
// speedup vs baseline: 1.5587x; 1.1059x over previous
#include <cuda_runtime.h>
#include <cuda_bf16.h>
#include <math.h>
#include <stdint.h>

#define B_ 4
#define C_ 256
#define H_ 128
#define W_ 128
#define HW_ (H_*W_)
#define NPIX_ (B_*HW_)
#define NT64 (NPIX_/64)      // 1024 GEMM tiles, 64 pixels each

typedef unsigned int u32;

// ---------------- global scratch ----------------
__device__ float g_xt[(size_t)NPIX_ * C_];                                 // 64 MB
__device__ __align__(16) __nv_bfloat16 gQ[(size_t)NT64 * 2 * 64 * 256];    // 64 MB
__device__ __align__(16) __nv_bfloat16 gX[(size_t)NT64 * 2 * 64 * 256];    // 64 MB
__device__ __align__(16) __nv_bfloat16 gW[2 * 2 * 256 * 256];              // 512 KB
__device__ __align__(16) float gP[(size_t)NPIX_ * 256];                    // 64 MB (parked Q)

// ---------------- PTX helpers ----------------
__device__ __forceinline__ u32 smem_u32(const void* p) {
    u32 a; asm("{ .reg .u64 t; cvta.to.shared.u64 t, %1; cvt.u32.u64 %0, t; }"
               : "=r"(a) : "l"(p));
    return a;
}
__device__ __forceinline__ void ldmx4(u32 addr, u32* r) {
    asm volatile("ldmatrix.sync.aligned.m8n8.x4.shared.b16 {%0,%1,%2,%3}, [%4];"
                 : "=r"(r[0]), "=r"(r[1]), "=r"(r[2]), "=r"(r[3]) : "r"(addr));
}
__device__ __forceinline__ void cpa16(u32 dst, const void* src) {
    asm volatile("cp.async.cg.shared.global [%0], [%1], 16;" :: "r"(dst), "l"(src));
}
#define CP_COMMIT() asm volatile("cp.async.commit_group;" ::: "memory")
#define CP_WAIT(n)  asm volatile("cp.async.wait_group %0;" :: "n"(n) : "memory")

__device__ __forceinline__ void mma_bf16(float* d, const u32* a, u32 b0, u32 b1) {
    asm volatile(
        "mma.sync.aligned.m16n8k16.row.col.f32.bf16.bf16.f32 "
        "{%0,%1,%2,%3},{%4,%5,%6,%7},{%8,%9},{%0,%1,%2,%3};"
        : "+f"(d[0]), "+f"(d[1]), "+f"(d[2]), "+f"(d[3])
        : "r"(a[0]), "r"(a[1]), "r"(a[2]), "r"(a[3]), "r"(b0), "r"(b1));
}

// ---------------------------------------------------------------------------
// Transpose x -> g_xt (NHWC fp32) AND gX (bf16 hi/lo, GEMM tile layout)
// ---------------------------------------------------------------------------
__global__ void k_tx(const float* __restrict__ x) {
    __shared__ float t[32][33];
    int b = blockIdx.z, s0 = blockIdx.x * 32, c0 = blockIdx.y * 32;
    int tx = threadIdx.x, ty = threadIdx.y;
    const float* xi = x + (size_t)b * C_ * HW_;
    float* xo = g_xt + (size_t)b * HW_ * C_;
#pragma unroll
    for (int i = 0; i < 32; i += 8)
        t[ty + i][tx] = xi[(size_t)(c0 + ty + i) * HW_ + s0 + tx];
    __syncthreads();
#pragma unroll
    for (int i = 0; i < 32; i += 8) {
        float v = t[tx][ty + i];
        int s = s0 + ty + i;
        xo[(size_t)s * C_ + c0 + tx] = v;
        int gp = b * HW_ + s;
        size_t tb = (size_t)(gp >> 6) * 32768 + (size_t)(gp & 63) * 256 + c0 + tx;
        __nv_bfloat16 h = __float2bfloat16_rn(v);
        gX[tb]         = h;
        gX[tb + 16384] = __float2bfloat16_rn(v - __bfloat162float(h));
    }
}

// ---------------------------------------------------------------------------
// Weight prep: w[o][c] fp32 -> gW[g][plane][o][k] bf16 (hi/lo split)
// ---------------------------------------------------------------------------
__global__ void k_wprep(const float* __restrict__ w0, const float* __restrict__ w1) {
    int g = blockIdx.x;
    int o = threadIdx.x;
    const float* w = g ? w1 : w0;
    __nv_bfloat16* hi = gW + ((size_t)(g * 2 + 0) * 256 + o) * 256;
    __nv_bfloat16* lo = gW + ((size_t)(g * 2 + 1) * 256 + o) * 256;
    for (int k = 0; k < 256; k++) {
        float a = w[o * 256 + k];
        __nv_bfloat16 h = __float2bfloat16_rn(a);
        hi[k] = h;
        lo[k] = __float2bfloat16_rn(a - __bfloat162float(h));
    }
}

// ---------------------------------------------------------------------------
// Gather: deformable 3x3 max-unfold -> gQ (bf16 hi/lo tiles)
// Block: 256 threads, 32 pixels (8 threads/pixel, 32 channels each)
// ---------------------------------------------------------------------------
__device__ __forceinline__ void split_store4(__nv_bfloat16* pHi, __nv_bfloat16* pLo, float4 v) {
    __nv_bfloat16 h0 = __float2bfloat16_rn(v.x), h1 = __float2bfloat16_rn(v.y);
    __nv_bfloat16 h2 = __float2bfloat16_rn(v.z), h3 = __float2bfloat16_rn(v.w);
    __nv_bfloat162 a = __halves2bfloat162(h0, h1), b = __halves2bfloat162(h2, h3);
    __nv_bfloat162 c = __halves2bfloat162(
        __float2bfloat16_rn(v.x - __bfloat162float(h0)),
        __float2bfloat16_rn(v.y - __bfloat162float(h1)));
    __nv_bfloat162 d = __halves2bfloat162(
        __float2bfloat16_rn(v.z - __bfloat162float(h2)),
        __float2bfloat16_rn(v.w - __bfloat162float(h3)));
    uint2 hv, lv;
    hv.x = *(u32*)&a; hv.y = *(u32*)&b;
    lv.x = *(u32*)&c; lv.y = *(u32*)&d;
    *(uint2*)pHi = hv;
    *(uint2*)pLo = lv;
}

__global__ __launch_bounds__(256)
void k_gather(const float* __restrict__ offset) {
    __shared__ float offs[18 * 32];
    const int tid  = threadIdx.x;
    const int base = blockIdx.x * 32;
    const int b    = base / HW_;
    const int rem  = base % HW_;
    const int y    = rem / W_;
    const int x0   = rem % W_;

    for (int i = tid; i < 18 * 32; i += 256) {
        int j = i >> 5, p = i & 31;
        offs[i] = offset[((size_t)b * 18 + j) * HW_ + y * W_ + x0 + p];
    }
    __syncthreads();

    const float* xtb = g_xt + (size_t)b * HW_ * C_;
    const int sub = tid & 7;
    const int p   = tid >> 3;
    const int pxi = x0 + p;
    const int tile = blockIdx.x >> 1;
    const int r    = ((blockIdx.x & 1) << 5) + p;

    float4 qm[8];
#pragma unroll
    for (int i = 0; i < 8; i++) { qm[i].x = qm[i].y = qm[i].z = qm[i].w = -3.4e38f; }

#pragma unroll
    for (int k = 0; k < 9; k++) {
        const int kh = k / 3 - 1, kw = k % 3 - 1;
        float py  = (float)(y + kh)   + offs[(2 * k) * 32 + p];
        float pxx = (float)(pxi + kw) + offs[(2 * k + 1) * 32 + p];
        float fy = floorf(py), fx = floorf(pxx);
        float wy = py - fy, wx = pxx - fx;
        int iy = (int)fy, ix = (int)fx;

        float4 acc[8];
#pragma unroll
        for (int i = 0; i < 8; i++) { acc[i].x = acc[i].y = acc[i].z = acc[i].w = 0.f; }

        float cw[4] = { (1.f - wy) * (1.f - wx), (1.f - wy) * wx,
                        wy * (1.f - wx),         wy * wx };
        int cy[4] = { iy, iy, iy + 1, iy + 1 };
        int cx[4] = { ix, ix + 1, ix, ix + 1 };
#pragma unroll
        for (int c4 = 0; c4 < 4; c4++) {
            if (cy[c4] >= 0 && cy[c4] < H_ && cx[c4] >= 0 && cx[c4] < W_) {
                const float4* cp = (const float4*)(xtb + (size_t)(cy[c4] * W_ + cx[c4]) * C_);
                float w = cw[c4];
#pragma unroll
                for (int i = 0; i < 8; i++) {
                    float4 v = cp[sub + 8 * i];
                    acc[i].x = fmaf(w, v.x, acc[i].x);
                    acc[i].y = fmaf(w, v.y, acc[i].y);
                    acc[i].z = fmaf(w, v.z, acc[i].z);
                    acc[i].w = fmaf(w, v.w, acc[i].w);
                }
            }
        }
#pragma unroll
        for (int i = 0; i < 8; i++) {
            qm[i].x = fmaxf(qm[i].x, acc[i].x);
            qm[i].y = fmaxf(qm[i].y, acc[i].y);
            qm[i].z = fmaxf(qm[i].z, acc[i].z);
            qm[i].w = fmaxf(qm[i].w, acc[i].w);
        }
    }

    size_t tbase = (size_t)tile * 32768 + (size_t)r * 256;
#pragma unroll
    for (int i = 0; i < 8; i++) {
        int c = 4 * (sub + 8 * i);
        split_store4(gQ + tbase + c, gQ + tbase + 16384 + c, qm[i]);
    }
}

// ---------------------------------------------------------------------------
// GEMM via mma.sync bf16 (split-precision, 3 terms) + stats epilogue.
// One CTA (256 threads, 8 warps 2m x 4n) per 64-pixel tile; 2 CTAs/SM.
// 3-stage cp.async pipeline, 1 barrier per k-step. Q parked in global gP.
// ---------------------------------------------------------------------------
#define ARS 48
#define SOFF_BIAS  0        // 512 f
#define SOFF_STATS 2048     // 4*5*64 f = 5120 B
#define SOFF_A     7168     // 3 stages x 6144 B  (2 planes x 64 rows x 48B)
#define SOFF_B     25600    // 3 stages x 24576 B (2 planes x 256 rows x 48B)
#define SMEM_TOTAL 99328

__global__ __launch_bounds__(256, 2)
void k_gemm(const float* __restrict__ gb0, const float* __restrict__ gb1,
            float* __restrict__ out) {
    extern __shared__ unsigned char sm[];
    float* bias  = (float*)(sm + SOFF_BIAS);
    float* stats = (float*)(sm + SOFF_STATS);
    const u32 smb = smem_u32(sm);
    const u32 smA = smb + SOFF_A;
    const u32 smB = smb + SOFF_B;

    const int tid = threadIdx.x, lane = tid & 31, wid = tid >> 5;
    const int mw = wid >> 2, nw = wid & 3;
    const int tile = blockIdx.x;

    bias[tid]       = gb0[tid];
    bias[256 + tid] = gb1[tid];

    // staging decomposition
    const int aPl = tid >> 7, aRow = (tid >> 1) & 63, aHf = tid & 1;
    const u32 aDst0 = smA + aPl * 3072 + aRow * ARS + aHf * 16;

    // ldmatrix lane addressing
    const int aLRow = lane & 15, aLCol = (lane >> 4) * 16;
    const int bLRow = ((lane >> 4) << 3) + (lane & 7), bLCol = ((lane >> 3) & 1) * 16;

    float* parkP = gP + (size_t)tile * 64 * 256;

    for (int ph = 0; ph < 2; ph++) {
        const __nv_bfloat16* Ab = (ph ? gX : gQ) + (size_t)tile * 32768;
        const __nv_bfloat16* Bb = gW + (size_t)ph * 131072;
        const __nv_bfloat16* aSrc = Ab + aPl * 16384 + aRow * 256 + aHf * 8;

        float acc[2][8][4];
#pragma unroll
        for (int s = 0; s < 2; s++)
#pragma unroll
            for (int t = 0; t < 8; t++)
#pragma unroll
                for (int j = 0; j < 4; j++) acc[s][t][j] = 0.f;

        // prologue: stage 0 and 1
#pragma unroll
        for (int st = 0; st < 2; st++) {
            cpa16(aDst0 + st * 6144, aSrc + st * 16);
#pragma unroll
            for (int i = 0; i < 4; i++) {
                int idx = tid + i * 256;
                int pl = idx >> 9, row = (idx >> 1) & 255, hf = idx & 1;
                cpa16(smB + st * 24576 + pl * 12288 + row * ARS + hf * 16,
                      Bb + pl * 65536 + row * 256 + st * 16 + hf * 8);
            }
            CP_COMMIT();
        }

        for (int ks = 0; ks < 16; ks++) {
            if (ks < 14) { CP_WAIT(1); } else { CP_WAIT(0); }
            __syncthreads();

            const int cur = ks % 3;
            const u32 Ac = smA + cur * 6144;
            const u32 Bc = smB + cur * 24576;

            u32 ah[2][4], al[2][4];
#pragma unroll
            for (int s = 0; s < 2; s++) {
                u32 arow = (u32)(mw * 32 + s * 16 + aLRow);
                ldmx4(Ac + arow * ARS + aLCol, ah[s]);
                ldmx4(Ac + 3072 + arow * ARS + aLCol, al[s]);
            }
#pragma unroll
            for (int tt = 0; tt < 4; tt++) {
                u32 brow = (u32)(nw * 64 + tt * 16 + bLRow);
                u32 bh[4], bl[4];
                ldmx4(Bc + brow * ARS + bLCol, bh);
                ldmx4(Bc + 12288 + brow * ARS + bLCol, bl);
#pragma unroll
                for (int half = 0; half < 2; half++) {
                    int t = tt * 2 + half;
                    u32 b0h = bh[half * 2], b1h = bh[half * 2 + 1];
                    u32 b0l = bl[half * 2], b1l = bl[half * 2 + 1];
#pragma unroll
                    for (int s = 0; s < 2; s++) {
                        mma_bf16(acc[s][t], ah[s], b0h, b1h);
                        mma_bf16(acc[s][t], ah[s], b0l, b1l);
                        mma_bf16(acc[s][t], al[s], b0h, b1h);
                    }
                }
            }

            if (ks < 14) {
                const int nst = (ks + 2) % 3;
                cpa16(aDst0 + nst * 6144, aSrc + (ks + 2) * 16);
#pragma unroll
                for (int i = 0; i < 4; i++) {
                    int idx = tid + i * 256;
                    int pl = idx >> 9, row = (idx >> 1) & 255, hf = idx & 1;
                    cpa16(smB + nst * 24576 + pl * 12288 + row * ARS + hf * 16,
                          Bb + pl * 65536 + row * 256 + (ks + 2) * 16 + hf * 8);
                }
                CP_COMMIT();
            }
        }
        __syncthreads();   // staging buffers reused by next phase

        if (ph == 0) {
            // park Q (+bias) in global
#pragma unroll
            for (int s = 0; s < 2; s++) {
                int r1 = mw * 32 + s * 16 + (lane >> 2);
#pragma unroll
                for (int t = 0; t < 8; t++) {
                    int n0 = nw * 64 + t * 8 + (lane & 3) * 2;
                    float2 v0 = make_float2(acc[s][t][0] + bias[n0], acc[s][t][1] + bias[n0 + 1]);
                    float2 v1 = make_float2(acc[s][t][2] + bias[n0], acc[s][t][3] + bias[n0 + 1]);
                    *(float2*)(parkP + r1 * 256 + n0) = v0;
                    *(float2*)(parkP + (r1 + 8) * 256 + n0) = v1;
                }
            }
        } else {
            // fold the 5 per-pixel stats
#pragma unroll
            for (int s = 0; s < 2; s++) {
                int r1 = mw * 32 + s * 16 + (lane >> 2);
                float st0[5] = {0, 0, 0, 0, 0}, st1[5] = {0, 0, 0, 0, 0};
#pragma unroll
                for (int t = 0; t < 8; t++) {
                    int n0 = nw * 64 + t * 8 + (lane & 3) * 2;
                    float bk0 = bias[256 + n0], bk1 = bias[256 + n0 + 1];
                    float2 q0 = *(float2*)(parkP + r1 * 256 + n0);
                    float2 q1 = *(float2*)(parkP + (r1 + 8) * 256 + n0);
                    float k0v = acc[s][t][0] + bk0, k1v = acc[s][t][1] + bk1;
                    float k2v = acc[s][t][2] + bk0, k3v = acc[s][t][3] + bk1;
                    st0[0] += q0.x + q0.y;  st0[1] += k0v + k1v;
                    st0[2] = fmaf(q0.x, q0.x, fmaf(q0.y, q0.y, st0[2]));
                    st0[3] = fmaf(k0v, k0v, fmaf(k1v, k1v, st0[3]));
                    st0[4] = fmaf(q0.x, k0v, fmaf(q0.y, k1v, st0[4]));
                    st1[0] += q1.x + q1.y;  st1[1] += k2v + k3v;
                    st1[2] = fmaf(q1.x, q1.x, fmaf(q1.y, q1.y, st1[2]));
                    st1[3] = fmaf(k2v, k2v, fmaf(k3v, k3v, st1[3]));
                    st1[4] = fmaf(q1.x, k2v, fmaf(q1.y, k3v, st1[4]));
                }
#pragma unroll
                for (int j = 0; j < 5; j++) {
                    st0[j] += __shfl_xor_sync(0xffffffffu, st0[j], 1);
                    st0[j] += __shfl_xor_sync(0xffffffffu, st0[j], 2);
                    st1[j] += __shfl_xor_sync(0xffffffffu, st1[j], 1);
                    st1[j] += __shfl_xor_sync(0xffffffffu, st1[j], 2);
                }
                if ((lane & 3) == 0) {
#pragma unroll
                    for (int j = 0; j < 5; j++) {
                        stats[(nw * 5 + j) * 64 + r1]     = st0[j];
                        stats[(nw * 5 + j) * 64 + r1 + 8] = st1[j];
                    }
                }
            }
            __syncthreads();
            if (tid < 64) {
                float sq = 0, sk = 0, sqq = 0, skk = 0, sqk = 0;
#pragma unroll
                for (int w = 0; w < 4; w++) {
                    sq  += stats[(w * 5 + 0) * 64 + tid];
                    sk  += stats[(w * 5 + 1) * 64 + tid];
                    sqq += stats[(w * 5 + 2) * 64 + tid];
                    skk += stats[(w * 5 + 3) * 64 + tid];
                    sqk += stats[(w * 5 + 4) * 64 + tid];
                }
                const float inv = 1.f / 256.f;
                float num = sqk - sq * sk * inv;
                float dq  = sqq - sq * sq * inv + 1e-5f;
                float dk  = skk - sk * sk * inv + 1e-5f;
                out[tile * 64 + tid] = num * rsqrtf(dq) * rsqrtf(dk);
            }
        }
    }
}

// ---------------------------------------------------------------------------
extern "C" void kernel_launch(void* const* d_in, const int* in_sizes, int n_in,
                              void* d_out, int out_size) {
    const float* x      = (const float*)d_in[0];
    const float* offset = (const float*)d_in[1];
    const float* w0     = (const float*)d_in[2];
    const float* b0     = (const float*)d_in[3];
    const float* w1     = (const float*)d_in[4];
    const float* b1     = (const float*)d_in[5];
    float* out = (float*)d_out;

    k_tx<<<dim3(HW_ / 32, C_ / 32, B_), dim3(32, 8)>>>(x);
    k_wprep<<<2, 256>>>(w0, w1);
    k_gather<<<NPIX_ / 32, 256>>>(offset);

    cudaFuncSetAttribute(k_gemm, cudaFuncAttributeMaxDynamicSharedMemorySize, SMEM_TOTAL);
    k_gemm<<<NT64, 256, SMEM_TOTAL>>>(b0, b1, out);
}